// round 11
// baseline (speedup 1.0000x reference)
#include <cuda_runtime.h>
#include <cuda_bf16.h>
#include <cstdint>

#define BB 4
#define C 256
#define L 4096
#define EPSV 1e-5f
#define NSPLIT 2

#if defined(__CUDA_ARCH_FEAT_SM103_ALL) || defined(__CUDA_ARCH_FEAT_SM100_ALL) || defined(__CUDA_ARCH_FAMILY_SPECIFIC__)
#define TC_OK 1
#else
#define TC_OK 0
#endif

// ---------------- device scratch ----------------
__device__ float g_scale[C];
__device__ float g_shift[C];
__device__ __align__(16) __nv_bfloat16 g_wbh[4 * C * C], g_wbl[4 * C * C];
__device__ __align__(16) __nv_bfloat16 g_xth[(size_t)BB * L * C], g_xtl[(size_t)BB * L * C];
__device__ float g_s[(size_t)BB * L * L];
__device__ float g_hp[NSPLIT][(size_t)BB * C * L];
__device__ __align__(16) __nv_bfloat16 g_qh[(size_t)BB * L * C], g_ql[(size_t)BB * L * C];
__device__ __align__(16) __nv_bfloat16 g_kh[(size_t)BB * L * C], g_kl[(size_t)BB * L * C];
__device__ __align__(16) __nv_bfloat16 g_vh[(size_t)BB * C * L], g_vl[(size_t)BB * C * L];
__device__ __align__(16) __nv_bfloat16 g_ph[(size_t)BB * L * L], g_pl[(size_t)BB * L * L];
__device__ __align__(16) __nv_bfloat16 g_hth[(size_t)BB * L * C], g_htl[(size_t)BB * L * C];

// ---------------- SMEM layout: A 2x32KB, B 2x32KB ----------------
#define SM_PTR   0
#define SM_MBAR0 8
#define SM_MBAR1 16
#define SM_A     1024
#define SM_B     (1024 + 65536)
#define SMEMSZ   (1024 + 131072)

#define IDESC_BF16 0x8400490u

// ---------------- fold-proof bf16 hi/lo split ----------------
__device__ __forceinline__ void split_bf16(float v, uint16_t& hb, uint16_t& lb) {
    float hf, r;
    asm("cvt.rn.bf16.f32 %0, %1;" : "=h"(hb) : "f"(v));
    asm("cvt.f32.bf16 %0, %1;"    : "=f"(hf) : "h"(hb));
    asm("sub.rn.f32 %0, %1, %2;"  : "=f"(r)  : "f"(v), "f"(hf));
    asm("cvt.rn.bf16.f32 %0, %1;" : "=h"(lb) : "f"(r));
}
__device__ __forceinline__ void wsplit2(__nv_bfloat16* h, __nv_bfloat16* l, size_t idx,
                                        float a, float b) {
    uint16_t ha, la, hbb, lbb;
    split_bf16(a, ha, la);
    split_bf16(b, hbb, lbb);
    uint32_t hp = (uint32_t)ha | ((uint32_t)hbb << 16);
    uint32_t lp = (uint32_t)la | ((uint32_t)lbb << 16);
    *(uint32_t*)((char*)h + idx * 2) = hp;
    *(uint32_t*)((char*)l + idx * 2) = lp;
}

// ---------------- tcgen05 helpers ----------------
__device__ __forceinline__ uint32_t smem_u32(const void* p) {
    uint32_t a;
    asm("{ .reg .u64 t; cvta.to.shared.u64 t, %1; cvt.u32.u64 %0, t; }" : "=r"(a) : "l"(p));
    return a;
}
__device__ __forceinline__ uint32_t elect1() {
    uint32_t p;
    asm volatile("{\n\t.reg .pred p;\n\telect.sync _|p, 0xFFFFFFFF;\n\tselp.b32 %0, 1, 0, p;\n\t}" : "=r"(p));
    return p;
}
__device__ __forceinline__ uint64_t make_desc(uint32_t addr) {
    return (2ULL << 61) | (1ULL << 46) | (64ULL << 32) | (1ULL << 16) |
           ((uint64_t)(addr >> 4) & 0x3FFF);
}
__device__ __forceinline__ void tc_alloc(uint32_t sptr) {
#if TC_OK
    asm volatile("tcgen05.alloc.cta_group::1.sync.aligned.shared::cta.b32 [%0], %1;"
                 :: "r"(sptr), "r"(512u) : "memory");
    asm volatile("tcgen05.relinquish_alloc_permit.cta_group::1.sync.aligned;");
#endif
}
__device__ __forceinline__ void tc_dealloc(uint32_t tmem) {
#if TC_OK
    asm volatile("tcgen05.dealloc.cta_group::1.sync.aligned.b32 %0, %1;" :: "r"(tmem), "r"(512u));
#endif
}
__device__ __forceinline__ void mma_bf16(uint32_t d, uint64_t ad, uint64_t bd, bool acc) {
#if TC_OK
    uint32_t e = acc ? 1u : 0u;
    asm volatile(
        "{\n\t.reg .pred p;\n\tsetp.ne.u32 p, %4, 0;\n\t"
        "tcgen05.mma.cta_group::1.kind::f16 [%0], %1, %2, %3, {%5, %5, %5, %5}, p;\n\t}"
        :: "r"(d), "l"(ad), "l"(bd), "r"(IDESC_BF16), "r"(e), "r"(0u) : "memory");
#endif
}
__device__ __forceinline__ void tc_commit(uint32_t mbar) {
#if TC_OK
    asm volatile("tcgen05.commit.cta_group::1.mbarrier::arrive::one.shared::cluster.b64 [%0];"
                 :: "r"(mbar) : "memory");
#endif
}
__device__ __forceinline__ void tc_fence_after() {
#if TC_OK
    asm volatile("tcgen05.fence::after_thread_sync;" ::: "memory");
#endif
}
__device__ __forceinline__ void ldtm32(uint32_t* r, uint32_t addr) {
#if TC_OK
    asm volatile(
        "tcgen05.ld.sync.aligned.32x32b.x32.b32 "
        "{%0, %1, %2, %3, %4, %5, %6, %7, "
        " %8, %9, %10, %11, %12, %13, %14, %15, "
        " %16, %17, %18, %19, %20, %21, %22, %23, "
        " %24, %25, %26, %27, %28, %29, %30, %31}, [%32];"
        : "=r"(r[0]),  "=r"(r[1]),  "=r"(r[2]),  "=r"(r[3]),
          "=r"(r[4]),  "=r"(r[5]),  "=r"(r[6]),  "=r"(r[7]),
          "=r"(r[8]),  "=r"(r[9]),  "=r"(r[10]), "=r"(r[11]),
          "=r"(r[12]), "=r"(r[13]), "=r"(r[14]), "=r"(r[15]),
          "=r"(r[16]), "=r"(r[17]), "=r"(r[18]), "=r"(r[19]),
          "=r"(r[20]), "=r"(r[21]), "=r"(r[22]), "=r"(r[23]),
          "=r"(r[24]), "=r"(r[25]), "=r"(r[26]), "=r"(r[27]),
          "=r"(r[28]), "=r"(r[29]), "=r"(r[30]), "=r"(r[31])
        : "r"(addr));
    asm volatile("tcgen05.wait::ld.sync.aligned;" ::: "memory");
#else
#pragma unroll
    for (int i = 0; i < 32; i++) r[i] = 0;
#endif
}
__device__ __forceinline__ void mbar_init(uint32_t a) {
    asm volatile("mbarrier.init.shared.b64 [%0], %1;" :: "r"(a), "r"(1u) : "memory");
}
__device__ __forceinline__ void mbar_wait(uint32_t a, int parity) {
    asm volatile(
        "{\n\t.reg .pred P;\n"
        "W_%=:\n\t"
        "mbarrier.try_wait.parity.acquire.cta.shared::cta.b64 P, [%0], %1, 0x989680;\n\t"
        "@P bra.uni D_%=;\n\t"
        "bra.uni W_%=;\n"
        "D_%=:\n\t}"
        :: "r"(a), "r"(parity) : "memory");
}

// ---------------- cp.async tile loader: A 256 rows, B 256 rows (SW128) ----------------
__device__ __forceinline__ void cpa_tiles(const __nv_bfloat16* __restrict__ A, int lda,
                                          const __nv_bfloat16* __restrict__ B, int ldb,
                                          int k0, uint32_t da, uint32_t db, int t) {
#pragma unroll
    for (int i = 0; i < 8; i++) {
        int idx = t + i * 256;
        int r = idx >> 3, cc = idx & 7;
        uint32_t off = r * 128 + cc * 16;
        asm volatile("cp.async.cg.shared.global [%0], [%1], 16;"
                     :: "r"(da + (off ^ ((off >> 3) & 0x70))),
                        "l"(A + (size_t)r * lda + k0 + cc * 8) : "memory");
    }
#pragma unroll
    for (int i = 0; i < 8; i++) {
        int idx = t + i * 256;
        int r = idx >> 3, cc = idx & 7;
        uint32_t off = r * 128 + cc * 16;
        asm volatile("cp.async.cg.shared.global [%0], [%1], 16;"
                     :: "r"(db + (off ^ ((off >> 3) & 0x70))),
                        "l"(B + (size_t)r * ldb + k0 + cc * 8) : "memory");
    }
}

__device__ __forceinline__ void seg_sel(const __nv_bfloat16* Ah, const __nv_bfloat16* Al,
                                        const __nv_bfloat16* Bh, const __nv_bfloat16* Bl,
                                        int ck, int nseg,
                                        const __nv_bfloat16*& Ap, const __nv_bfloat16*& Bp, int& k0) {
    int seg = (ck >= nseg) + (ck >= 2 * nseg);
    Ap = (seg == 1) ? Al : Ah;
    Bp = (seg == 2) ? Bl : Bh;
    k0 = (ck - seg * nseg) * 64;
}

// D[256x256] = Ah*Bh^T + Al*Bh^T + Ah*Bl^T   (M=256 dual-accumulator, cp.async pipeline)
__device__ __forceinline__ uint32_t run_gemm3(const __nv_bfloat16* __restrict__ Ah,
                                              const __nv_bfloat16* __restrict__ Al,
                                              const __nv_bfloat16* __restrict__ Bh,
                                              const __nv_bfloat16* __restrict__ Bl,
                                              int lda, int ldb, int nseg, char* smem) {
    const int t = threadIdx.x;
    const int nch = 3 * nseg;
    uint32_t sb = smem_u32(smem);
    if (t < 32) tc_alloc(sb + SM_PTR);
    if (t == 0) { mbar_init(sb + SM_MBAR0); mbar_init(sb + SM_MBAR1); }
    __syncthreads();
    uint32_t tmem;
    asm volatile("ld.shared.b32 %0, [%1];" : "=r"(tmem) : "r"(sb + SM_PTR));

    int ph0 = 0, ph1 = 0;
    cpa_tiles(Ah, lda, Bh, ldb, 0, sb + SM_A, sb + SM_B, t);
    asm volatile("cp.async.commit_group;" ::: "memory");

    for (int ck = 0; ck < nch; ck++) {
        const int pb = ck & 1;
        if (ck + 1 < nch) {
            const int nb = pb ^ 1;
            if (ck >= 1) {
                if (nb == 0) { mbar_wait(sb + SM_MBAR0, ph0); ph0 ^= 1; }
                else         { mbar_wait(sb + SM_MBAR1, ph1); ph1 ^= 1; }
            }
            const __nv_bfloat16 *Ap, *Bp;
            int k0;
            seg_sel(Ah, Al, Bh, Bl, ck + 1, nseg, Ap, Bp, k0);
            cpa_tiles(Ap, lda, Bp, ldb, k0,
                      sb + SM_A + nb * 32768, sb + SM_B + nb * 32768, t);
            asm volatile("cp.async.commit_group;" ::: "memory");
            asm volatile("cp.async.wait_group 1;" ::: "memory");
        } else {
            asm volatile("cp.async.wait_group 0;" ::: "memory");
        }
        __syncthreads();
        if (t < 32) {
            asm volatile("fence.proxy.async.shared::cta;" ::: "memory");
            if (elect1()) {
                uint64_t bd = make_desc(sb + SM_B + pb * 32768);
#pragma unroll
                for (int acc = 0; acc < 2; acc++) {
                    uint64_t ad = make_desc(sb + SM_A + pb * 32768 + acc * 16384);
#pragma unroll
                    for (int s = 0; s < 4; s++)
                        mma_bf16(tmem + acc * 256, ad + 2 * s, bd + 2 * s, (ck | s) != 0);
                }
                tc_commit(sb + SM_MBAR0 + pb * 8);
            }
        }
    }
    if (((nch - 1) & 1) == 0) mbar_wait(sb + SM_MBAR0, ph0);
    else                      mbar_wait(sb + SM_MBAR1, ph1);
    tc_fence_after();
    return tmem;
}

__device__ __forceinline__ void gemm_dealloc(uint32_t tmem) {
    __syncthreads();
    if (threadIdx.x < 32) tc_dealloc(tmem);
}

// ---------------- 1) BN stats ----------------
__global__ void __launch_bounds__(256) bn_stats(const float* __restrict__ x,
                                                const float* __restrict__ gamma,
                                                const float* __restrict__ beta) {
    int c = blockIdx.x, t = threadIdx.x;
    float s = 0.f, sq = 0.f;
    for (int b = 0; b < BB; b++) {
        const float* p = x + ((size_t)b * C + c) * L;
        for (int l = t; l < L; l += 256) { float v = p[l]; s += v; sq += v * v; }
    }
    __shared__ float sh0[256], sh1[256];
    sh0[t] = s; sh1[t] = sq;
    __syncthreads();
    for (int o = 128; o > 0; o >>= 1) {
        if (t < o) { sh0[t] += sh0[t + o]; sh1[t] += sh1[t + o]; }
        __syncthreads();
    }
    if (t == 0) {
        const float inv_n = 1.f / (float)(BB * L);
        float mean = sh0[0] * inv_n;
        float var  = sh1[0] * inv_n - mean * mean;
        float rs   = rsqrtf(var + EPSV);
        float sc   = gamma[c] * rs;
        g_scale[c] = sc;
        g_shift[c] = beta[c] - mean * sc;
    }
}

// ---------------- 2) split RAW weights ----------------
__global__ void __launch_bounds__(256) split_weights(const float* __restrict__ wq,
                                                     const float* __restrict__ wk,
                                                     const float* __restrict__ wv,
                                                     const float* __restrict__ wp) {
    int mat = blockIdx.y;
    const float* w = (mat == 0) ? wq : ((mat == 1) ? wk : ((mat == 2) ? wv : wp));
    size_t i = ((size_t)blockIdx.x * 256 + threadIdx.x) * 2;
    float2 v = *(const float2*)(w + i);
    wsplit2(g_wbh + (size_t)mat * C * C, g_wbl + (size_t)mat * C * C, i, v.x, v.y);
}

// ---------------- 3) normalize + transpose + split x ----------------
__global__ void __launch_bounds__(256) prep_xsplit(const float* __restrict__ x) {
    __shared__ float tile[32][33];
    int bi = blockIdx.z;
    int l0 = blockIdx.x * 32, c0 = blockIdx.y * 32;
    int tx = threadIdx.x, ty = threadIdx.y;
#pragma unroll
    for (int j = 0; j < 4; j++) {
        int c = c0 + ty + j * 8;
        float v = x[((size_t)bi * C + c) * L + l0 + tx];
        tile[ty + j * 8][tx] = v * g_scale[c] + g_shift[c];
    }
    __syncthreads();
#pragma unroll
    for (int j = 0; j < 4; j++) {
        int l = l0 + ty + j * 8;
        float v = tile[tx][ty + j * 8];
        uint16_t hb, lb;
        split_bf16(v, hb, lb);
        size_t idx = ((size_t)bi * L + l) * C + c0 + tx;
        *(uint16_t*)&g_xth[idx] = hb;
        *(uint16_t*)&g_xtl[idx] = lb;
    }
}

// ---------------- 4) q/k TC projection (M=256 l-rows) ----------------
__global__ void __launch_bounds__(256) qk_gemm_tc(const float* __restrict__ bq,
                                                  const float* __restrict__ bk) {
    extern __shared__ char smem[];
    int bi = blockIdx.y >> 1, mat = blockIdx.y & 1;
    int l0 = blockIdx.x * 256;
    size_t arow = ((size_t)bi * L + l0) * C;
    uint32_t tmem = run_gemm3(g_xth + arow, g_xtl + arow,
                              g_wbh + (size_t)mat * C * C, g_wbl + (size_t)mat * C * C, C, C, 4, smem);

    int t = threadIdx.x, wt = t & 127, wg = t >> 7;
    int row = wg * 128 + wt;
    size_t drow = ((size_t)bi * L + l0 + row) * C;
    __nv_bfloat16* dh = mat ? g_kh : g_qh;
    __nv_bfloat16* dl = mat ? g_kl : g_ql;
    const float* bias = mat ? bk : bq;
    uint32_t tm = tmem + wg * 256;
    for (int nb = 0; nb < 8; nb++) {
        uint32_t r[32];
        ldtm32(r, tm + nb * 32);
#pragma unroll
        for (int j = 0; j < 16; j++) {
            int n = nb * 32 + 2 * j;
            wsplit2(dh, dl, drow + n, __uint_as_float(r[2 * j + 0]) + bias[n + 0],
                                      __uint_as_float(r[2 * j + 1]) + bias[n + 1]);
        }
    }
    gemm_dealloc(tmem);
}

// ---------------- 5) v TC projection (M=256 = all C rows) ----------------
__global__ void __launch_bounds__(256) v_gemm_tc(const float* __restrict__ bv) {
    extern __shared__ char smem[];
    int bi = blockIdx.y, l0 = blockIdx.x * 256;
    size_t brow = ((size_t)bi * L + l0) * C;
    uint32_t tmem = run_gemm3(g_wbh + 2 * C * C, g_wbl + 2 * C * C,
                              g_xth + brow, g_xtl + brow, C, C, 4, smem);

    int t = threadIdx.x, wt = t & 127, wg = t >> 7;
    int o = wg * 128 + wt;
    float bias = bv[o];
    size_t drow = ((size_t)bi * C + o) * L + l0;
    uint32_t tm = tmem + wg * 256;
    for (int nb = 0; nb < 8; nb++) {
        uint32_t r[32];
        ldtm32(r, tm + nb * 32);
#pragma unroll
        for (int j = 0; j < 16; j++) {
            int n = nb * 32 + 2 * j;
            wsplit2(g_vh, g_vl, drow + n, __uint_as_float(r[2 * j + 0]) + bias,
                                          __uint_as_float(r[2 * j + 1]) + bias);
        }
    }
    gemm_dealloc(tmem);
}

// ---------------- 6) scores TC (M=256 i-rows) ----------------
__global__ void __launch_bounds__(256) scores_gemm_tc() {
    extern __shared__ char smem[];
    int bi = blockIdx.z, i0 = blockIdx.y * 256, j0 = blockIdx.x * 256;
    size_t arow = ((size_t)bi * L + i0) * C;
    size_t brow = ((size_t)bi * L + j0) * C;
    uint32_t tmem = run_gemm3(g_qh + arow, g_ql + arow, g_kh + brow, g_kl + brow, C, C, 4, smem);

    int t = threadIdx.x, wt = t & 127, wg = t >> 7;
    int row = wg * 128 + wt;
    float* dst = g_s + ((size_t)bi * L + i0 + row) * L + j0;
    const float scale = 0.0625f;
    uint32_t tm = tmem + wg * 256;
    for (int nb = 0; nb < 8; nb++) {
        uint32_t r[32];
        ldtm32(r, tm + nb * 32);
#pragma unroll
        for (int j = 0; j < 8; j++) {
            float4 v;
            v.x = __uint_as_float(r[4 * j + 0]) * scale;
            v.y = __uint_as_float(r[4 * j + 1]) * scale;
            v.z = __uint_as_float(r[4 * j + 2]) * scale;
            v.w = __uint_as_float(r[4 * j + 3]) * scale;
            *(float4*)(dst + nb * 32 + 4 * j) = v;
        }
    }
    gemm_dealloc(tmem);
}

// ---------------- 7) softmax rows -> ph/pl ----------------
__global__ void __launch_bounds__(256) softmax_rows() {
    size_t row = blockIdx.x;
    const float* p = g_s + row * (size_t)L;
    const int t = threadIdx.x;
    float2 r[8];
    float mx = -1e30f;
#pragma unroll
    for (int i = 0; i < 8; i++) {
        r[i] = *(const float2*)(p + i * 512 + t * 2);
        mx = fmaxf(mx, fmaxf(r[i].x, r[i].y));
    }
#pragma unroll
    for (int o = 16; o; o >>= 1) mx = fmaxf(mx, __shfl_xor_sync(0xffffffffu, mx, o));
    __shared__ float sm[8];
    if ((t & 31) == 0) sm[t >> 5] = mx;
    __syncthreads();
    float bm = sm[0];
#pragma unroll
    for (int i = 1; i < 8; i++) bm = fmaxf(bm, sm[i]);
    float s = 0.f;
#pragma unroll
    for (int i = 0; i < 8; i++) {
        r[i].x = __expf(r[i].x - bm);
        r[i].y = __expf(r[i].y - bm);
        s += r[i].x + r[i].y;
    }
#pragma unroll
    for (int o = 16; o; o >>= 1) s += __shfl_xor_sync(0xffffffffu, s, o);
    __syncthreads();
    if ((t & 31) == 0) sm[t >> 5] = s;
    __syncthreads();
    float tot = 0.f;
#pragma unroll
    for (int i = 0; i < 8; i++) tot += sm[i];
    float inv = 1.f / tot;
    size_t base = row * (size_t)L;
#pragma unroll
    for (int i = 0; i < 8; i++)
        wsplit2(g_ph, g_pl, base + i * 512 + t * 2, r[i].x * inv, r[i].y * inv);
}

// ---------------- 8) AV TC, split-K (M=256 i-rows, N=256 c) ----------------
__global__ void __launch_bounds__(256) av_gemm_tc() {
    extern __shared__ char smem[];
    int bi = blockIdx.z, ks = blockIdx.y, i0 = blockIdx.x * 256;
    const int koff = ks * (L / NSPLIT);
    size_t arow = ((size_t)bi * L + i0) * L + koff;
    size_t brow = (size_t)bi * C * L + koff;
    uint32_t tmem = run_gemm3(g_ph + arow, g_pl + arow, g_vh + brow, g_vl + brow,
                              L, L, (L / NSPLIT) / 64, smem);

    int t = threadIdx.x, wt = t & 127, wg = t >> 7;
    int row = wg * 128 + wt;
    float* hb = g_hp[ks] + (size_t)bi * C * L;
    uint32_t tm = tmem + wg * 256;
    for (int nb = 0; nb < 8; nb++) {
        uint32_t r[32];
        ldtm32(r, tm + nb * 32);
#pragma unroll
        for (int j = 0; j < 32; j++) {
            int c = nb * 32 + j;
            hb[(size_t)c * L + i0 + row] = __uint_as_float(r[j]);
        }
    }
    gemm_dealloc(tmem);
}

// ---------------- 9) reduce partials + transpose + split h ----------------
__global__ void __launch_bounds__(256) reduce_split_h() {
    __shared__ float tile[32][33];
    int bi = blockIdx.z;
    int l0 = blockIdx.x * 32, c0 = blockIdx.y * 32;
    int tx = threadIdx.x, ty = threadIdx.y;
#pragma unroll
    for (int j = 0; j < 4; j++) {
        int c = c0 + ty + j * 8;
        size_t idx = ((size_t)bi * C + c) * L + l0 + tx;
        float s = g_hp[0][idx] + g_hp[1][idx];
        tile[ty + j * 8][tx] = s;
    }
    __syncthreads();
#pragma unroll
    for (int j = 0; j < 4; j++) {
        int l = l0 + ty + j * 8;
        float v = tile[tx][ty + j * 8];
        uint16_t hb, lb;
        split_bf16(v, hb, lb);
        size_t idx = ((size_t)bi * L + l) * C + c0 + tx;
        *(uint16_t*)&g_hth[idx] = hb;
        *(uint16_t*)&g_htl[idx] = lb;
    }
}

// ---------------- 10) proj TC (M=256 = all C rows) + bias + residual ----------------
__global__ void __launch_bounds__(256) proj_gemm_tc(const float* __restrict__ x,
                                                    const float* __restrict__ bp,
                                                    float* __restrict__ out) {
    extern __shared__ char smem[];
    int bi = blockIdx.y, l0 = blockIdx.x * 256;
    size_t brow = ((size_t)bi * L + l0) * C;
    uint32_t tmem = run_gemm3(g_wbh + 3 * C * C, g_wbl + 3 * C * C,
                              g_hth + brow, g_htl + brow, C, C, 4, smem);

    int t = threadIdx.x, wt = t & 127, wg = t >> 7;
    int o = wg * 128 + wt;
    float bias = bp[o];
    size_t base = ((size_t)bi * C + o) * L + l0;
    uint32_t tm = tmem + wg * 256;
    for (int nb = 0; nb < 8; nb++) {
        uint32_t r[32];
        ldtm32(r, tm + nb * 32);
#pragma unroll
        for (int j = 0; j < 8; j++) {
            float4 xr = *(const float4*)(x + base + nb * 32 + 4 * j);
            float4 v;
            v.x = __uint_as_float(r[4 * j + 0]) + bias + xr.x;
            v.y = __uint_as_float(r[4 * j + 1]) + bias + xr.y;
            v.z = __uint_as_float(r[4 * j + 2]) + bias + xr.z;
            v.w = __uint_as_float(r[4 * j + 3]) + bias + xr.w;
            *(float4*)(out + base + nb * 32 + 4 * j) = v;
        }
    }
    gemm_dealloc(tmem);
}

// ---------------- launch ----------------
extern "C" void kernel_launch(void* const* d_in, const int* in_sizes, int n_in,
                              void* d_out, int out_size) {
    const float* x     = (const float*)d_in[0];
    const float* gamma = (const float*)d_in[1];
    const float* beta  = (const float*)d_in[2];
    const float* wq    = (const float*)d_in[3];
    const float* bq    = (const float*)d_in[4];
    const float* wk    = (const float*)d_in[5];
    const float* bk    = (const float*)d_in[6];
    const float* wv    = (const float*)d_in[7];
    const float* bv    = (const float*)d_in[8];
    const float* wp    = (const float*)d_in[9];
    const float* bp    = (const float*)d_in[10];
    float* out = (float*)d_out;

    cudaFuncSetAttribute(qk_gemm_tc,     cudaFuncAttributeMaxDynamicSharedMemorySize, SMEMSZ);
    cudaFuncSetAttribute(v_gemm_tc,      cudaFuncAttributeMaxDynamicSharedMemorySize, SMEMSZ);
    cudaFuncSetAttribute(scores_gemm_tc, cudaFuncAttributeMaxDynamicSharedMemorySize, SMEMSZ);
    cudaFuncSetAttribute(av_gemm_tc,     cudaFuncAttributeMaxDynamicSharedMemorySize, SMEMSZ);
    cudaFuncSetAttribute(proj_gemm_tc,   cudaFuncAttributeMaxDynamicSharedMemorySize, SMEMSZ);

    bn_stats<<<C, 256>>>(x, gamma, beta);
    split_weights<<<dim3((C * C / 2) / 256, 4), 256>>>(wq, wk, wv, wp);
    prep_xsplit<<<dim3(L / 32, C / 32, BB), dim3(32, 8)>>>(x);
    qk_gemm_tc<<<dim3(L / 256, BB * 2), 256, SMEMSZ>>>(bq, bk);
    v_gemm_tc<<<dim3(L / 256, BB), 256, SMEMSZ>>>(bv);
    scores_gemm_tc<<<dim3(L / 256, L / 256, BB), 256, SMEMSZ>>>();
    softmax_rows<<<BB * L, 256>>>();
    av_gemm_tc<<<dim3(L / 256, NSPLIT, BB), 256, SMEMSZ>>>();
    reduce_split_h<<<dim3(L / 32, C / 32, BB), dim3(32, 8)>>>();
    proj_gemm_tc<<<dim3(L / 256, BB), 256, SMEMSZ>>>(x, bp, out);
}